// round 1
// baseline (speedup 1.0000x reference)
#include <cuda_runtime.h>
#include <math.h>

// Problem dims
#define TT   512   // sequence length
#define DD   256   // in_vocab_size
#define HH   256   // hidden size
#define H2   512   // 2*H (output row width)

// chunked scan config
#define NCHUNK 16
#define LCH    32  // NCHUNK*LCH == TT

// GEMM tiling
#define TM 32
#define TN 64
#define TK 32

// Device scratch (no dynamic allocation allowed)
__device__ float g_bx[TT * H2];      // [t][h'] : h'<256 -> Bx1, h'>=256 -> Bx2
__device__ float g_E[NCHUNK * H2];   // per-chunk local end states

// ---------------------------------------------------------------------------
// GEMM: g_bx[t][h'] = dot(x[t, :], B[h', :])  where B = concat(B_c1, B_c2)
// Tiles: 32(t) x 64(h') x 32(k), 128 threads/block, 4x4 micro-tile per thread.
// ---------------------------------------------------------------------------
__global__ __launch_bounds__(128) void gemm_kernel(
    const float* __restrict__ x,
    const float* __restrict__ B1,
    const float* __restrict__ B2)
{
    __shared__ float xs[TK][TM + 4];  // stride 36 floats (16B-aligned rows)
    __shared__ float bs[TK][TN + 4];  // stride 68 floats

    const int tBase = blockIdx.x * TM;
    const int hBase = blockIdx.y * TN;
    const float* __restrict__ Bp =
        (hBase < HH) ? (B1 + hBase * DD) : (B2 + (hBase - HH) * DD);

    const int tid = threadIdx.x;
    const int kk  = tid & 31;
    const int r0  = tid >> 5;              // 0..3
    const int m_base = (tid >> 4) * 4;     // 0..28
    const int n_base = (tid & 15) * 4;     // 0..60

    float acc[4][4];
#pragma unroll
    for (int i = 0; i < 4; i++)
#pragma unroll
        for (int jx = 0; jx < 4; jx++) acc[i][jx] = 0.f;

    for (int k0 = 0; k0 < DD; k0 += TK) {
        // load x tile: 32x32 (coalesced along k), store transposed xs[k][m]
#pragma unroll
        for (int i = 0; i < 8; i++) {
            int mm = r0 + i * 4;
            xs[kk][mm] = x[(tBase + mm) * DD + k0 + kk];
        }
        // load B tile: 64x32, store transposed bs[k][n]
#pragma unroll
        for (int i = 0; i < 16; i++) {
            int nn = r0 + i * 4;
            bs[kk][nn] = Bp[nn * DD + k0 + kk];
        }
        __syncthreads();

#pragma unroll
        for (int k = 0; k < TK; k++) {
            float4 a = *(const float4*)&xs[k][m_base];
            float4 b = *(const float4*)&bs[k][n_base];
            float am[4] = {a.x, a.y, a.z, a.w};
            float bn[4] = {b.x, b.y, b.z, b.w};
#pragma unroll
            for (int i = 0; i < 4; i++)
#pragma unroll
                for (int jx = 0; jx < 4; jx++)
                    acc[i][jx] = fmaf(am[i], bn[jx], acc[i][jx]);
        }
        __syncthreads();
    }

#pragma unroll
    for (int i = 0; i < 4; i++) {
        float4 v = make_float4(acc[i][0], acc[i][1], acc[i][2], acc[i][3]);
        *(float4*)&g_bx[(tBase + m_base + i) * H2 + hBase + n_base] = v;
    }
}

// ---------------------------------------------------------------------------
// Per-channel rotation coefficients (recomputed per thread; MUFU is cheap)
// ---------------------------------------------------------------------------
__device__ __forceinline__ void coeffs(const float* __restrict__ lamda,
                                       const float* __restrict__ theta,
                                       int h, float& c, float& s, float& gam)
{
    float e = expf(lamda[h]);
    float y = expf(-e);
    float z = expf(theta[h]);
    gam = sqrtf(fmaxf(1.0f - y * y, 0.0f));
    float cz, sz;
    sincosf(z, &sz, &cz);
    c = y * cz;
    s = y * sz;
}

// ---------------------------------------------------------------------------
// Pass A: zero-init local scans per chunk; write local h to out; save chunk end.
// grid = NCHUNK blocks, 256 threads (one per channel)
// ---------------------------------------------------------------------------
__global__ __launch_bounds__(256) void scanA_kernel(
    const float* __restrict__ lamda,
    const float* __restrict__ theta,
    float* __restrict__ out)
{
    const int h = threadIdx.x;
    const int j = blockIdx.x;
    float c, s, gam;
    coeffs(lamda, theta, h, c, s, gam);

    float l1 = 0.f, l2 = 0.f;
    const int t0 = j * LCH;
#pragma unroll 4
    for (int tt = 0; tt < LCH; tt++) {
        int t = t0 + tt;
        float b1 = g_bx[t * H2 + h];
        float b2 = g_bx[t * H2 + HH + h];
        float n1 = fmaf(c, l1, fmaf(-s, l2, gam * b1));
        float n2 = fmaf(c, l2, fmaf( s, l1, gam * b2));
        l1 = n1; l2 = n2;
        out[t * H2 + h]      = l1;
        out[t * H2 + HH + h] = l2;
    }
    g_E[j * H2 + h]      = l1;
    g_E[j * H2 + HH + h] = l2;
}

// ---------------------------------------------------------------------------
// Pass C: for chunk j>=1, compute carry = sum_{i<j} R^{L(j-1-i)} E[i]
// via p = R^L p + E[i]; then add R^{tt+1} * carry into out over the chunk.
// grid = NCHUNK-1 blocks (chunk 0 has zero carry), 256 threads.
// ---------------------------------------------------------------------------
__global__ __launch_bounds__(256) void scanC_kernel(
    const float* __restrict__ lamda,
    const float* __restrict__ theta,
    float* __restrict__ out)
{
    const int h = threadIdx.x;
    const int j = blockIdx.x + 1;
    float c, s, gam;
    coeffs(lamda, theta, h, c, s, gam);
    (void)gam;

    // R^32 = (c + i s)^32 via 5 complex squarings
    float a = c, b = s;
#pragma unroll
    for (int q = 0; q < 5; q++) {
        float na = a * a - b * b;
        float nb = 2.0f * a * b;
        a = na; b = nb;
    }

    float p1 = 0.f, p2 = 0.f;
    for (int i = 0; i < j; i++) {
        float e1 = g_E[i * H2 + h];
        float e2 = g_E[i * H2 + HH + h];
        float n1 = fmaf(a, p1, fmaf(-b, p2, e1));
        float n2 = fmaf(a, p2, fmaf( b, p1, e2));
        p1 = n1; p2 = n2;
    }

    const int t0 = j * LCH;
#pragma unroll 4
    for (int tt = 0; tt < LCH; tt++) {
        float n1 = fmaf(c, p1, -s * p2);
        float n2 = fmaf(c, p2,  s * p1);
        p1 = n1; p2 = n2;
        int t = t0 + tt;
        out[t * H2 + h]      += p1;
        out[t * H2 + HH + h] += p2;
    }
}

// ---------------------------------------------------------------------------
extern "C" void kernel_launch(void* const* d_in, const int* in_sizes, int n_in,
                              void* d_out, int out_size)
{
    const float* x     = (const float*)d_in[0];  // [512, 256]
    const float* lamda = (const float*)d_in[1];  // [256]
    const float* theta = (const float*)d_in[2];  // [256]
    const float* B1    = (const float*)d_in[3];  // [256, 256]
    const float* B2    = (const float*)d_in[4];  // [256, 256]
    float* out = (float*)d_out;                  // [512, 512]

    dim3 ggrid(TT / TM, H2 / TN);   // (16, 8) = 128 blocks
    gemm_kernel<<<ggrid, 128>>>(x, B1, B2);
    scanA_kernel<<<NCHUNK, 256>>>(lamda, theta, out);
    scanC_kernel<<<NCHUNK - 1, 256>>>(lamda, theta, out);
}

// round 2
// speedup vs baseline: 2.3529x; 2.3529x over previous
#include <cuda_runtime.h>
#include <math.h>

// Problem dims
#define TT   512
#define DD   256
#define HH   256
#define H2   512

#define NCHUNK 16
#define LCH    32

// smem layout (floats)
#define STRA 260                 // padded row stride for k-major tiles (16B aligned)
#define AS_OFF 0                 // as[32][260]
#define BS_OFF (32 * STRA)       // bs[64][260]
#define SS_OFF (BS_OFF + 64 * STRA) // Ss[32][68] staging for scan
#define SS_STR 68
#define SMEM_FLOATS (SS_OFF + 32 * SS_STR)
#define SMEM_BYTES (SMEM_FLOATS * 4)

__device__ float g_E[NCHUNK * H2];   // per-chunk local end states

__device__ __forceinline__ void coeffs(const float* __restrict__ lamda,
                                       const float* __restrict__ theta,
                                       int h, float& c, float& s, float& gam)
{
    float e = expf(lamda[h]);
    float y = expf(-e);
    float z = expf(theta[h]);
    gam = sqrtf(fmaxf(1.0f - y * y, 0.0f));
    float cz, sz;
    sincosf(z, &sz, &cz);
    c = y * cz;
    s = y * sz;
}

// ---------------------------------------------------------------------------
// Fused kernel: block (j = chunk, g = 32-channel group).
// Phase 1: stage x[t0:t0+32, :] (32x256) and 64 B rows (B1[ch], B2[ch]) in smem.
// Phase 2: 32t x 64c x 256k GEMM, 256 threads, 2x4 micro-tile, float4 over k.
// Phase 3: local zero-init scan over 32 steps for 32 channels; write out + g_E.
// ---------------------------------------------------------------------------
__global__ __launch_bounds__(256, 1) void fused_kernel(
    const float* __restrict__ x,
    const float* __restrict__ B1,
    const float* __restrict__ B2,
    const float* __restrict__ lamda,
    const float* __restrict__ theta,
    float* __restrict__ out)
{
    extern __shared__ float sm[];
    float* as = sm + AS_OFF;
    float* bs = sm + BS_OFF;
    float* Ss = sm + SS_OFF;

    const int j = blockIdx.x;          // chunk
    const int g = blockIdx.y;          // channel group
    const int t0 = j * LCH;
    const int ch0 = g * 32;
    const int tid = threadIdx.x;

    // ---- coefficients for scan threads (computed early, overlaps loads) ----
    float cc = 0.f, ss_ = 0.f, gam = 0.f;
    if (tid < 32) coeffs(lamda, theta, ch0 + tid, cc, ss_, gam);

    // ---- stage operands ----
    const float4* x4 = (const float4*)x;
#pragma unroll
    for (int i = 0; i < 8; i++) {
        int idx = i * 256 + tid;
        int row = idx >> 6;            // 0..31
        int q   = idx & 63;            // 0..63
        float4 v = x4[(t0 + row) * 64 + q];
        *(float4*)&as[row * STRA + 4 * q] = v;
    }
#pragma unroll
    for (int i = 0; i < 16; i++) {
        int idx = i * 256 + tid;
        int row = idx >> 6;            // 0..63
        int q   = idx & 63;
        const float4* Bsrc = (row < 32)
            ? (const float4*)(B1 + (ch0 + row) * DD)
            : (const float4*)(B2 + (ch0 + row - 32) * DD);
        float4 v = Bsrc[q];
        *(float4*)&bs[row * STRA + 4 * q] = v;
    }
    __syncthreads();

    // ---- GEMM: thread -> t in {tIdx, tIdx+16}, c in {cIdx + 16*i} ----
    const int tIdx = tid >> 4;         // 0..15
    const int cIdx = tid & 15;         // 0..15

    float acc[2][4];
#pragma unroll
    for (int i = 0; i < 2; i++)
#pragma unroll
        for (int jb = 0; jb < 4; jb++) acc[i][jb] = 0.f;

#pragma unroll 4
    for (int kq = 0; kq < 64; kq++) {
        float4 a0 = *(const float4*)&as[tIdx * STRA + 4 * kq];
        float4 a1 = *(const float4*)&as[(tIdx + 16) * STRA + 4 * kq];
        float4 b0 = *(const float4*)&bs[(cIdx     ) * STRA + 4 * kq];
        float4 b1 = *(const float4*)&bs[(cIdx + 16) * STRA + 4 * kq];
        float4 b2 = *(const float4*)&bs[(cIdx + 32) * STRA + 4 * kq];
        float4 b3 = *(const float4*)&bs[(cIdx + 48) * STRA + 4 * kq];

        acc[0][0] = fmaf(a0.x, b0.x, acc[0][0]); acc[0][0] = fmaf(a0.y, b0.y, acc[0][0]);
        acc[0][0] = fmaf(a0.z, b0.z, acc[0][0]); acc[0][0] = fmaf(a0.w, b0.w, acc[0][0]);
        acc[0][1] = fmaf(a0.x, b1.x, acc[0][1]); acc[0][1] = fmaf(a0.y, b1.y, acc[0][1]);
        acc[0][1] = fmaf(a0.z, b1.z, acc[0][1]); acc[0][1] = fmaf(a0.w, b1.w, acc[0][1]);
        acc[0][2] = fmaf(a0.x, b2.x, acc[0][2]); acc[0][2] = fmaf(a0.y, b2.y, acc[0][2]);
        acc[0][2] = fmaf(a0.z, b2.z, acc[0][2]); acc[0][2] = fmaf(a0.w, b2.w, acc[0][2]);
        acc[0][3] = fmaf(a0.x, b3.x, acc[0][3]); acc[0][3] = fmaf(a0.y, b3.y, acc[0][3]);
        acc[0][3] = fmaf(a0.z, b3.z, acc[0][3]); acc[0][3] = fmaf(a0.w, b3.w, acc[0][3]);
        acc[1][0] = fmaf(a1.x, b0.x, acc[1][0]); acc[1][0] = fmaf(a1.y, b0.y, acc[1][0]);
        acc[1][0] = fmaf(a1.z, b0.z, acc[1][0]); acc[1][0] = fmaf(a1.w, b0.w, acc[1][0]);
        acc[1][1] = fmaf(a1.x, b1.x, acc[1][1]); acc[1][1] = fmaf(a1.y, b1.y, acc[1][1]);
        acc[1][1] = fmaf(a1.z, b1.z, acc[1][1]); acc[1][1] = fmaf(a1.w, b1.w, acc[1][1]);
        acc[1][2] = fmaf(a1.x, b2.x, acc[1][2]); acc[1][2] = fmaf(a1.y, b2.y, acc[1][2]);
        acc[1][2] = fmaf(a1.z, b2.z, acc[1][2]); acc[1][2] = fmaf(a1.w, b2.w, acc[1][2]);
        acc[1][3] = fmaf(a1.x, b3.x, acc[1][3]); acc[1][3] = fmaf(a1.y, b3.y, acc[1][3]);
        acc[1][3] = fmaf(a1.z, b3.z, acc[1][3]); acc[1][3] = fmaf(a1.w, b3.w, acc[1][3]);
    }
    __syncthreads();   // all smem reads done; Ss region may overlap usage order

    // ---- stage tile for scan ----
#pragma unroll
    for (int i = 0; i < 2; i++)
#pragma unroll
        for (int jb = 0; jb < 4; jb++)
            Ss[(tIdx + 16 * i) * SS_STR + cIdx + 16 * jb] = acc[i][jb];
    __syncthreads();

    // ---- local scan: 32 channel-threads, 32 steps ----
    if (tid < 32) {
        const int ch = tid;
        float l1 = 0.f, l2 = 0.f;
        float* o1 = out + t0 * H2 + ch0 + ch;
        float* o2 = o1 + HH;
#pragma unroll 8
        for (int tt = 0; tt < LCH; tt++) {
            float b1 = Ss[tt * SS_STR + ch];
            float b2 = Ss[tt * SS_STR + 32 + ch];
            float n1 = fmaf(cc, l1, fmaf(-ss_, l2, gam * b1));
            float n2 = fmaf(cc, l2, fmaf( ss_, l1, gam * b2));
            l1 = n1; l2 = n2;
            o1[tt * H2] = l1;
            o2[tt * H2] = l2;
        }
        g_E[j * H2 + ch0 + ch]      = l1;
        g_E[j * H2 + HH + ch0 + ch] = l2;
    }
}

// ---------------------------------------------------------------------------
// Correction: block (j = chunk 1..15, q = t-quarter 0..3), 256 threads = channels.
// carry = sum_{i<j} R^{32(j-1-i)} E[i]; each quarter starts at R^{8q}*carry,
// then 8 steps of p <- R p, out += p.
// ---------------------------------------------------------------------------
__global__ __launch_bounds__(256) void fix_kernel(
    const float* __restrict__ lamda,
    const float* __restrict__ theta,
    float* __restrict__ out)
{
    const int h = threadIdx.x;
    const int j = blockIdx.x + 1;
    const int q = blockIdx.y;

    float c, s, gam;
    coeffs(lamda, theta, h, c, s, gam);
    (void)gam;

    // powers of R = (c + i s)
    float a = c, b = s;
#pragma unroll
    for (int it = 0; it < 3; it++) { float na = a*a - b*b, nb = 2.f*a*b; a = na; b = nb; }
    float a8 = a, b8 = b;            // R^8
#pragma unroll
    for (int it = 0; it < 2; it++) { float na = a*a - b*b, nb = 2.f*a*b; a = na; b = nb; }
    float a32 = a, b32 = b;          // R^32

    // carry over previous chunks
    float p1 = 0.f, p2 = 0.f;
    for (int i = 0; i < j; i++) {
        float e1 = g_E[i * H2 + h];
        float e2 = g_E[i * H2 + HH + h];
        float n1 = fmaf(a32, p1, fmaf(-b32, p2, e1));
        float n2 = fmaf(a32, p2, fmaf( b32, p1, e2));
        p1 = n1; p2 = n2;
    }
    // jump to quarter start: p *= R^(8q)
    for (int it = 0; it < q; it++) {
        float n1 = a8 * p1 - b8 * p2;
        float n2 = fmaf(a8, p2, b8 * p1);
        p1 = n1; p2 = n2;
    }

    const int t0 = j * LCH + q * 8;
    float* o1 = out + t0 * H2 + h;
    float* o2 = o1 + HH;
#pragma unroll
    for (int tt = 0; tt < 8; tt++) {
        float n1 = fmaf(c, p1, -s * p2);
        float n2 = fmaf(c, p2,  s * p1);
        p1 = n1; p2 = n2;
        o1[tt * H2] += p1;
        o2[tt * H2] += p2;
    }
}

// ---------------------------------------------------------------------------
extern "C" void kernel_launch(void* const* d_in, const int* in_sizes, int n_in,
                              void* d_out, int out_size)
{
    const float* x     = (const float*)d_in[0];
    const float* lamda = (const float*)d_in[1];
    const float* theta = (const float*)d_in[2];
    const float* B1    = (const float*)d_in[3];
    const float* B2    = (const float*)d_in[4];
    float* out = (float*)d_out;

    static bool attr_set = false;
    if (!attr_set) {
        cudaFuncSetAttribute(fused_kernel,
                             cudaFuncAttributeMaxDynamicSharedMemorySize,
                             SMEM_BYTES);
        attr_set = true;
    }

    dim3 grid(NCHUNK, HH / 32);                 // (16, 8) = 128 blocks
    fused_kernel<<<grid, 256, SMEM_BYTES>>>(x, B1, B2, lamda, theta, out);
    dim3 fgrid(NCHUNK - 1, 4);                  // 60 blocks
    fix_kernel<<<fgrid, 256>>>(lamda, theta, out);
}

// round 3
// speedup vs baseline: 3.0467x; 1.2948x over previous
#include <cuda_runtime.h>
#include <math.h>

// Problem dims
#define TT   512
#define DD   256
#define HH   256
#define H2   512

#define NCHUNK 16
#define LCH    32
#define NBLOCKS (NCHUNK * (HH / 32))   // 128

// smem layout (floats)
#define STRA 260                       // padded k-major row stride
#define AS_OFF 0                       // as[32][260]
#define BS_OFF (32 * STRA)             // bs[64][260]
#define SS_OFF (BS_OFF + 64 * STRA)    // Ss[32][68]
#define SS_STR 68
#define SMEM_FLOATS (SS_OFF + 32 * SS_STR)
#define SMEM_BYTES (SMEM_FLOATS * 4)

__device__ float g_E[NCHUNK * H2];     // per-chunk local end states
__device__ int   g_ctr = 0;            // monotonic barrier counter (replay-safe)

__device__ __forceinline__ void coeffs(const float* __restrict__ lamda,
                                       const float* __restrict__ theta,
                                       int h, float& c, float& s, float& gam)
{
    float e = expf(lamda[h]);
    float y = expf(-e);
    float z = expf(theta[h]);
    gam = sqrtf(fmaxf(1.0f - y * y, 0.0f));
    float cz, sz;
    sincosf(z, &sz, &cz);
    c = y * cz;
    s = y * sz;
}

// ---------------------------------------------------------------------------
// One persistent kernel. Block (j = chunk, g = 32-channel group):
//  1) stage x[32,256] + B[64,256] in smem
//  2) GEMM 32t x 64c x 256k, 256 threads (2 k-halves x 8x16), 4x4 strided
//  3) smem reduction of k-halves into Ss
//  4) local zero-init scan (32 threads), h-locals kept in Ss, ends -> g_E
//  5) software grid barrier (all 128 blocks co-resident)
//  6) carry from g_E (unrolled, MLP) + correction; single write of out
// ---------------------------------------------------------------------------
__global__ __launch_bounds__(256, 1) void rtrl_kernel(
    const float* __restrict__ x,
    const float* __restrict__ B1,
    const float* __restrict__ B2,
    const float* __restrict__ lamda,
    const float* __restrict__ theta,
    float* __restrict__ out)
{
    extern __shared__ float sm[];
    float* as = sm + AS_OFF;
    float* bs = sm + BS_OFF;
    float* Ss = sm + SS_OFF;

    const int j   = blockIdx.x;        // chunk
    const int g   = blockIdx.y;        // channel group
    const int t0  = j * LCH;
    const int ch0 = g * 32;
    const int tid = threadIdx.x;
    const int ch  = tid & 31;
    const int h   = ch0 + ch;

    // per-channel rotation coefficients (all threads; overlaps staging)
    float cc, ss_, gam;
    coeffs(lamda, theta, h, cc, ss_, gam);

    // ---- stage operands ----
    const float4* x4 = (const float4*)x;
#pragma unroll
    for (int i = 0; i < 8; i++) {
        int idx = i * 256 + tid;
        int row = idx >> 6;
        int q   = idx & 63;
        float4 v = x4[(t0 + row) * 64 + q];
        *(float4*)&as[row * STRA + 4 * q] = v;
    }
#pragma unroll
    for (int i = 0; i < 16; i++) {
        int idx = i * 256 + tid;
        int row = idx >> 6;            // 0..63
        int q   = idx & 63;
        const float4* Bsrc = (row < 32)
            ? (const float4*)(B1 + (ch0 + row) * DD)
            : (const float4*)(B2 + (ch0 + row - 32) * DD);
        float4 v = Bsrc[q];
        *(float4*)&bs[row * STRA + 4 * q] = v;
    }
    __syncthreads();

    // ---- GEMM: k-split halves, 4x4 strided micro-tile ----
    const int half = tid >> 7;         // 0/1 -> k in [0,128) / [128,256)
    const int t7   = tid & 127;
    const int tsub = t7 >> 4;          // 0..7  -> t rows {tsub+8i}
    const int csub = t7 & 15;          // 0..15 -> cols  {csub+16i}
    const int kq0  = half * 32;        // float4-quad offset

    float acc[4][4];
#pragma unroll
    for (int i = 0; i < 4; i++)
#pragma unroll
        for (int jb = 0; jb < 4; jb++) acc[i][jb] = 0.f;

#pragma unroll 8
    for (int kq = 0; kq < 32; kq++) {
        int kf = (kq0 + kq) * 4;
        float4 av[4], bv[4];
#pragma unroll
        for (int i = 0; i < 4; i++)
            av[i] = *(const float4*)&as[(tsub + 8 * i) * STRA + kf];
#pragma unroll
        for (int i = 0; i < 4; i++)
            bv[i] = *(const float4*)&bs[(csub + 16 * i) * STRA + kf];
#pragma unroll
        for (int i = 0; i < 4; i++) {
#pragma unroll
            for (int jb = 0; jb < 4; jb++) {
                acc[i][jb] = fmaf(av[i].x, bv[jb].x, acc[i][jb]);
                acc[i][jb] = fmaf(av[i].y, bv[jb].y, acc[i][jb]);
                acc[i][jb] = fmaf(av[i].z, bv[jb].z, acc[i][jb]);
                acc[i][jb] = fmaf(av[i].w, bv[jb].w, acc[i][jb]);
            }
        }
    }
    __syncthreads();  // done reading as/bs (Ss region is separate anyway)

    // ---- reduce k-halves into Ss ----
    if (half) {
#pragma unroll
        for (int i = 0; i < 4; i++)
#pragma unroll
            for (int jb = 0; jb < 4; jb++)
                Ss[(tsub + 8 * i) * SS_STR + csub + 16 * jb] = acc[i][jb];
    }
    __syncthreads();
    if (!half) {
#pragma unroll
        for (int i = 0; i < 4; i++)
#pragma unroll
            for (int jb = 0; jb < 4; jb++) {
                int idx = (tsub + 8 * i) * SS_STR + csub + 16 * jb;
                Ss[idx] += acc[i][jb];
            }
    }
    __syncthreads();

    // ---- local zero-init scan; keep h-locals in Ss; ends -> g_E ----
    if (tid < 32) {
        float l1 = 0.f, l2 = 0.f;
#pragma unroll 8
        for (int tt = 0; tt < LCH; tt++) {
            float b1 = Ss[tt * SS_STR + ch];
            float b2 = Ss[tt * SS_STR + 32 + ch];
            float n1 = fmaf(cc, l1, fmaf(-ss_, l2, gam * b1));
            float n2 = fmaf(cc, l2, fmaf( ss_, l1, gam * b2));
            l1 = n1; l2 = n2;
            Ss[tt * SS_STR + ch]      = l1;
            Ss[tt * SS_STR + 32 + ch] = l2;
        }
        g_E[j * H2 + h]      = l1;
        g_E[j * H2 + HH + h] = l2;
        __threadfence();
    }
    __syncthreads();

    // ---- software grid barrier (all 128 blocks resident: grid <= SMs, 1/SM) ----
    if (tid == 0) {
        __threadfence();
        int ticket = atomicAdd(&g_ctr, 1);
        int target = ((ticket >> 7) + 1) << 7;   // (launch_epoch+1)*128
        while (*((volatile int*)&g_ctr) < target) { /* spin */ }
        __threadfence();
    }
    __syncthreads();

    // ---- carry from previous chunks (unrolled, batched loads) ----
    float a4 = cc, b4 = ss_;
#pragma unroll
    for (int it = 0; it < 2; it++) { float na = a4*a4 - b4*b4, nb = 2.f*a4*b4; a4 = na; b4 = nb; }
    float a32 = a4, b32 = b4;
#pragma unroll
    for (int it = 0; it < 3; it++) { float na = a32*a32 - b32*b32, nb = 2.f*a32*b32; a32 = na; b32 = nb; }

    float p1 = 0.f, p2 = 0.f;
#pragma unroll
    for (int i = 0; i < NCHUNK - 1; i++) {
        if (i < j) {
            float e1 = __ldcg(&g_E[i * H2 + h]);
            float e2 = __ldcg(&g_E[i * H2 + HH + h]);
            float n1 = fmaf(a32, p1, fmaf(-b32, p2, e1));
            float n2 = fmaf(a32, p2, fmaf( b32, p1, e2));
            p1 = n1; p2 = n2;
        }
    }

    // ---- apply correction + single store of out ----
    const int q = tid >> 5;            // 0..7, t-slice of 4
    for (int it = 0; it < q; it++) {   // p *= R^4 per slice skipped
        float n1 = a4 * p1 - b4 * p2;
        float n2 = fmaf(a4, p2, b4 * p1);
        p1 = n1; p2 = n2;
    }

    const int tq = 4 * q;
#pragma unroll
    for (int i = 0; i < 4; i++) {
        float n1 = fmaf(cc, p1, -ss_ * p2);
        float n2 = fmaf(cc, p2,  ss_ * p1);
        p1 = n1; p2 = n2;
        int tt = tq + i;
        out[(t0 + tt) * H2 + h]      = Ss[tt * SS_STR + ch]      + p1;
        out[(t0 + tt) * H2 + HH + h] = Ss[tt * SS_STR + 32 + ch] + p2;
    }
}

// ---------------------------------------------------------------------------
extern "C" void kernel_launch(void* const* d_in, const int* in_sizes, int n_in,
                              void* d_out, int out_size)
{
    const float* x     = (const float*)d_in[0];
    const float* lamda = (const float*)d_in[1];
    const float* theta = (const float*)d_in[2];
    const float* B1    = (const float*)d_in[3];
    const float* B2    = (const float*)d_in[4];
    float* out = (float*)d_out;

    static bool attr_set = false;
    if (!attr_set) {
        cudaFuncSetAttribute(rtrl_kernel,
                             cudaFuncAttributeMaxDynamicSharedMemorySize,
                             SMEM_BYTES);
        attr_set = true;
    }

    dim3 grid(NCHUNK, HH / 32);        // (16, 8) = 128 blocks, all co-resident
    rtrl_kernel<<<grid, 256, SMEM_BYTES>>>(x, B1, B2, lamda, theta, out);
}

// round 4
// speedup vs baseline: 3.1000x; 1.0175x over previous
#include <cuda_runtime.h>
#include <math.h>
#include <stdint.h>

// Problem dims
#define TT   512
#define DD   256
#define HH   256
#define H2   512

#define NCHUNK 16
#define LCH    32
#define NBLOCKS 128

// smem layout (floats)
#define STRA 260                       // padded k-major row stride (16B-aligned rows)
#define AS_OFF 0                       // as[32][260]
#define BS_OFF (32 * STRA)             // bs[64][260]
#define SS_OFF (BS_OFF + 64 * STRA)    // Ss[32][68]
#define SS_STR 68
#define ES_OFF AS_OFF                  // Es[8][64] reuses as[] after GEMM
#define SMEM_FLOATS (SS_OFF + 32 * SS_STR)
#define SMEM_BYTES (SMEM_FLOATS * 4)

__device__ float g_E[NCHUNK * H2];     // per-chunk end states
__device__ int   g_ctr = 0;            // monotonic barrier counter (replay-safe)

// packed fp32x2 FMA (Blackwell): acc.lo += a.lo*b.lo ; acc.hi += a.hi*b.hi
#define FMA2(acc, a, b) \
    asm("fma.rn.f32x2 %0, %1, %2, %0;" : "+l"(acc) : "l"(a), "l"(b))

__device__ __forceinline__ float f32x2_sum(unsigned long long v) {
    float lo, hi;
    asm("mov.b64 {%0, %1}, %2;" : "=f"(lo), "=f"(hi) : "l"(v));
    return lo + hi;
}

__device__ __forceinline__ void cp16(float* smem_dst, const void* gsrc) {
    uint32_t sa = (uint32_t)__cvta_generic_to_shared(smem_dst);
    asm volatile("cp.async.cg.shared.global [%0], [%1], 16;" :: "r"(sa), "l"(gsrc));
}
#define CP_COMMIT() asm volatile("cp.async.commit_group;" ::: "memory")
#define CP_WAIT(n)  asm volatile("cp.async.wait_group %0;" :: "n"(n) : "memory")

__device__ __forceinline__ void coeffs(const float* __restrict__ lamda,
                                       const float* __restrict__ theta,
                                       int h, float& c, float& s, float& gam)
{
    float e = expf(lamda[h]);
    float y = expf(-e);
    float z = expf(theta[h]);
    gam = sqrtf(fmaxf(1.0f - y * y, 0.0f));
    float cz, sz;
    sincosf(z, &sz, &cz);
    c = y * cz;
    s = y * sz;
}

// ---------------------------------------------------------------------------
__global__ __launch_bounds__(256, 1) void rtrl_kernel(
    const float* __restrict__ x,
    const float* __restrict__ B1,
    const float* __restrict__ B2,
    const float* __restrict__ lamda,
    const float* __restrict__ theta,
    float* __restrict__ out)
{
    extern __shared__ float sm[];
    float* as = sm + AS_OFF;
    float* bs = sm + BS_OFF;
    float* Ss = sm + SS_OFF;
    float* Es = sm + ES_OFF;

    const int j   = blockIdx.x;        // chunk
    const int g   = blockIdx.y;        // channel group
    const int t0  = j * LCH;
    const int ch0 = g * 32;
    const int tid = threadIdx.x;
    const int ch  = tid & 31;
    const int sc  = tid >> 5;          // 0..7 (subchunk / t-slice)
    const int h   = ch0 + ch;

    float cc, ss_, gam;
    coeffs(lamda, theta, h, cc, ss_, gam);

    // ---- async staging: stage s covers k-strips {s, s+2} (strip = 16 quads) ----
    const float4* x4 = (const float4*)x;
#pragma unroll
    for (int s = 0; s < 2; s++) {
#pragma unroll
        for (int i = 0; i < 4; i++) {
            int idx = i * 256 + tid;
            int row = idx >> 5;                    // 0..31
            int qq  = idx & 31;
            int q   = ((qq >> 4) * 2 + s) * 16 + (qq & 15);
            cp16(&as[row * STRA + 4 * q], &x4[(t0 + row) * 64 + q]);
        }
#pragma unroll
        for (int i = 0; i < 8; i++) {
            int idx = i * 256 + tid;
            int row = idx >> 5;                    // 0..63
            int qq  = idx & 31;
            int q   = ((qq >> 4) * 2 + s) * 16 + (qq & 15);
            const float4* Bsrc = (row < 32)
                ? (const float4*)(B1 + (ch0 + row) * DD)
                : (const float4*)(B2 + (ch0 + row - 32) * DD);
            cp16(&bs[row * STRA + 4 * q], Bsrc + q);
        }
        CP_COMMIT();
    }

    // ---- GEMM: k-split halves, 4x4 strided micro-tile, f32x2 accumulators ----
    const int half = tid >> 7;         // 0/1 -> k quads [0,32) / [32,64)
    const int t7   = tid & 127;
    const int tsub = t7 >> 4;          // rows {tsub+8i}
    const int csub = t7 & 15;          // cols {csub+16i}
    const int kq0  = half * 32;

    unsigned long long acc[4][4];
#pragma unroll
    for (int i = 0; i < 4; i++)
#pragma unroll
        for (int jb = 0; jb < 4; jb++) acc[i][jb] = 0ull;

    CP_WAIT(1);
    __syncthreads();                   // stage A (strips 0,2) resident

#pragma unroll
    for (int ph = 0; ph < 2; ph++) {
        if (ph == 1) { CP_WAIT(0); __syncthreads(); }  // stage B resident
#pragma unroll 8
        for (int kq = ph * 16; kq < ph * 16 + 16; kq++) {
            int kf = (kq0 + kq) * 4;
            ulonglong2 av[4], bv[4];
#pragma unroll
            for (int i = 0; i < 4; i++)
                av[i] = *(const ulonglong2*)&as[(tsub + 8 * i) * STRA + kf];
#pragma unroll
            for (int i = 0; i < 4; i++)
                bv[i] = *(const ulonglong2*)&bs[(csub + 16 * i) * STRA + kf];
#pragma unroll
            for (int i = 0; i < 4; i++) {
#pragma unroll
                for (int jb = 0; jb < 4; jb++) {
                    FMA2(acc[i][jb], av[i].x, bv[jb].x);
                    FMA2(acc[i][jb], av[i].y, bv[jb].y);
                }
            }
        }
    }
    __syncthreads();

    // ---- reduce k-halves into Ss ----
    if (half) {
#pragma unroll
        for (int i = 0; i < 4; i++)
#pragma unroll
            for (int jb = 0; jb < 4; jb++)
                Ss[(tsub + 8 * i) * SS_STR + csub + 16 * jb] = f32x2_sum(acc[i][jb]);
    }
    __syncthreads();
    if (!half) {
#pragma unroll
        for (int i = 0; i < 4; i++)
#pragma unroll
            for (int jb = 0; jb < 4; jb++)
                Ss[(tsub + 8 * i) * SS_STR + csub + 16 * jb] += f32x2_sum(acc[i][jb]);
    }
    __syncthreads();

    // ---- parallel in-chunk scan: 8 subchunks of 4 steps, per channel ----
    float rl1[4], rl2[4];
    {
        float l1 = 0.f, l2 = 0.f;
#pragma unroll
        for (int i = 0; i < 4; i++) {
            int tt = 4 * sc + i;
            float b1 = Ss[tt * SS_STR + ch];
            float b2 = Ss[tt * SS_STR + 32 + ch];
            float n1 = fmaf(cc, l1, fmaf(-ss_, l2, gam * b1));
            float n2 = fmaf(cc, l2, fmaf( ss_, l1, gam * b2));
            l1 = n1; l2 = n2;
            rl1[i] = l1; rl2[i] = l2;
        }
        // publish subchunk end states (reuses as[] region, done with GEMM)
        Es[sc * 64 + ch]      = l1;
        Es[sc * 64 + 32 + ch] = l2;
    }
    __syncthreads();

    // rotation powers
    float a4 = cc, b4 = ss_;
#pragma unroll
    for (int it = 0; it < 2; it++) { float na = a4*a4 - b4*b4, nb = 2.f*a4*b4; a4 = na; b4 = nb; }
    float a32 = a4, b32 = b4;
#pragma unroll
    for (int it = 0; it < 3; it++) { float na = a32*a32 - b32*b32, nb = 2.f*a32*b32; a32 = na; b32 = nb; }

    // compose subchunk carry P (state at start of subchunk sc) and correct locals
    {
        float p1 = 0.f, p2 = 0.f;
#pragma unroll
        for (int u = 0; u < 7; u++) {
            if (u < sc) {
                float e1 = Es[u * 64 + ch];
                float e2 = Es[u * 64 + 32 + ch];
                float n1 = fmaf(a4, p1, fmaf(-b4, p2, e1));
                float n2 = fmaf(a4, p2, fmaf( b4, p1, e2));
                p1 = n1; p2 = n2;
            }
        }
#pragma unroll
        for (int i = 0; i < 4; i++) {
            float n1 = fmaf(cc, p1, -ss_ * p2);
            float n2 = fmaf(cc, p2,  ss_ * p1);
            p1 = n1; p2 = n2;
            rl1[i] += p1; rl2[i] += p2;
        }
    }
    // chunk end state = corrected local at tt=31 (thread sc==7)
    if (sc == 7) {
        g_E[j * H2 + h]      = rl1[3];
        g_E[j * H2 + HH + h] = rl2[3];
        __threadfence();
    }
    __syncthreads();

    // ---- software grid barrier (128 blocks, all co-resident) ----
    if (tid == 0) {
        __threadfence();
        int ticket = atomicAdd(&g_ctr, 1);
        int target = ((ticket >> 7) + 1) << 7;
        while (*((volatile int*)&g_ctr) < target) { }
        __threadfence();
    }
    __syncthreads();

    // ---- cross-chunk carry + final single store of out ----
    float p1 = 0.f, p2 = 0.f;
#pragma unroll
    for (int i = 0; i < NCHUNK - 1; i++) {
        if (i < j) {
            float e1 = __ldcg(&g_E[i * H2 + h]);
            float e2 = __ldcg(&g_E[i * H2 + HH + h]);
            float n1 = fmaf(a32, p1, fmaf(-b32, p2, e1));
            float n2 = fmaf(a32, p2, fmaf( b32, p1, e2));
            p1 = n1; p2 = n2;
        }
    }
    // rotate carry to this thread's t-slice start
    for (int it = 0; it < sc; it++) {
        float n1 = a4 * p1 - b4 * p2;
        float n2 = fmaf(a4, p2, b4 * p1);
        p1 = n1; p2 = n2;
    }
#pragma unroll
    for (int i = 0; i < 4; i++) {
        float n1 = fmaf(cc, p1, -ss_ * p2);
        float n2 = fmaf(cc, p2,  ss_ * p1);
        p1 = n1; p2 = n2;
        int tt = 4 * sc + i;
        out[(t0 + tt) * H2 + h]      = rl1[i] + p1;
        out[(t0 + tt) * H2 + HH + h] = rl2[i] + p2;
    }
}

// ---------------------------------------------------------------------------
extern "C" void kernel_launch(void* const* d_in, const int* in_sizes, int n_in,
                              void* d_out, int out_size)
{
    const float* x     = (const float*)d_in[0];
    const float* lamda = (const float*)d_in[1];
    const float* theta = (const float*)d_in[2];
    const float* B1    = (const float*)d_in[3];
    const float* B2    = (const float*)d_in[4];
    float* out = (float*)d_out;

    static bool attr_set = false;
    if (!attr_set) {
        cudaFuncSetAttribute(rtrl_kernel,
                             cudaFuncAttributeMaxDynamicSharedMemorySize,
                             SMEM_BYTES);
        attr_set = true;
    }

    dim3 grid(NCHUNK, HH / 32);        // (16, 8) = 128 blocks, all co-resident
    rtrl_kernel<<<grid, 256, SMEM_BYTES>>>(x, B1, B2, lamda, theta, out);
}

// round 5
// speedup vs baseline: 3.1078x; 1.0025x over previous
#include <cuda_runtime.h>
#include <math.h>
#include <stdint.h>

// Problem dims
#define TT   512
#define DD   256
#define HH   256
#define H2   512

#define NCHUNK 16
#define LCH    32
#define NBLOCKS 128
#define NTHR   512

// smem layout (floats)
#define STRA 260                        // padded k-major row stride
#define AS_OFF 0                        // as[32][260]
#define BS_OFF (32 * STRA)              // bs[64][260]
#define P_OFF  (BS_OFF + 64 * STRA)     // P[4][32][65] GEMM partials
#define P_QS   (32 * 65)
#define P_TS   65
#define ES_OFF (P_OFF + 4 * P_QS)       // Es[16][64] subchunk ends
#define SMEM_FLOATS (ES_OFF + 16 * 64)
#define SMEM_BYTES (SMEM_FLOATS * 4)    // ~134 KB

__device__ float g_E[NCHUNK * H2];      // per-chunk end states
__device__ int   g_ctr = 0;             // monotonic barrier counter (replay-safe)

#define FMA2(acc, a, b) \
    asm("fma.rn.f32x2 %0, %1, %2, %0;" : "+l"(acc) : "l"(a), "l"(b))

__device__ __forceinline__ float f32x2_sum(unsigned long long v) {
    float lo, hi;
    asm("mov.b64 {%0, %1}, %2;" : "=f"(lo), "=f"(hi) : "l"(v));
    return lo + hi;
}

__device__ __forceinline__ void cp16(float* smem_dst, const void* gsrc) {
    uint32_t sa = (uint32_t)__cvta_generic_to_shared(smem_dst);
    asm volatile("cp.async.cg.shared.global [%0], [%1], 16;" :: "r"(sa), "l"(gsrc));
}
#define CP_COMMIT() asm volatile("cp.async.commit_group;" ::: "memory")
#define CP_WAIT0()  asm volatile("cp.async.wait_group 0;" ::: "memory")
#define BARN(id, n) asm volatile("bar.sync %0, %1;" :: "r"(id), "r"(n) : "memory")

// complex multiply helper: (r1,r2) = (a,b)*(p1,p2)
__device__ __forceinline__ void cmul(float a, float b, float& p1, float& p2) {
    float n1 = a * p1 - b * p2;
    float n2 = fmaf(a, p2, b * p1);
    p1 = n1; p2 = n2;
}

__device__ __forceinline__ void coeffs(const float* __restrict__ lamda,
                                       const float* __restrict__ theta,
                                       int h, float& c, float& s, float& gam)
{
    float e = expf(lamda[h]);
    float y = expf(-e);
    float z = expf(theta[h]);
    gam = sqrtf(fmaxf(1.0f - y * y, 0.0f));
    float cz, sz;
    sincosf(z, &sz, &cz);
    c = y * cz;
    s = y * sz;
}

// ---------------------------------------------------------------------------
__global__ __launch_bounds__(NTHR, 1) void rtrl_kernel(
    const float* __restrict__ x,
    const float* __restrict__ B1,
    const float* __restrict__ B2,
    const float* __restrict__ lamda,
    const float* __restrict__ theta,
    float* __restrict__ out)
{
    extern __shared__ float sm[];
    float* as = sm + AS_OFF;
    float* bs = sm + BS_OFF;
    float* P  = sm + P_OFF;
    float* Es = sm + ES_OFF;

    const int j   = blockIdx.x;         // chunk
    const int g   = blockIdx.y;         // channel group
    const int t0  = j * LCH;
    const int ch0 = g * 32;
    const int tid = threadIdx.x;
    const int ch  = tid & 31;
    const int sc  = tid >> 5;           // 0..15 subchunk (2 steps each)
    const int h   = ch0 + ch;

    // ---- per-quarter staging: quarter q loads only k-strip q (24 KB) ----
    const int q  = tid >> 7;            // 0..3
    const int r  = tid & 127;
    const float4* x4 = (const float4*)x;
#pragma unroll
    for (int i = 0; i < 4; i++) {       // as strip: 32 rows x 16 quads
        int idx = i * 128 + r;
        int row = idx >> 4;
        int qd  = 16 * q + (idx & 15);
        cp16(&as[row * STRA + 4 * qd], &x4[(t0 + row) * 64 + qd]);
    }
#pragma unroll
    for (int i = 0; i < 8; i++) {       // bs strip: 64 rows x 16 quads
        int idx = i * 128 + r;
        int row = idx >> 4;
        int qd  = 16 * q + (idx & 15);
        const float4* Bsrc = (row < 32)
            ? (const float4*)(B1 + (ch0 + row) * DD)
            : (const float4*)(B2 + (ch0 + row - 32) * DD);
        cp16(&bs[row * STRA + 4 * qd], Bsrc + qd);
    }
    CP_COMMIT();

    // per-channel rotation coefficients (overlaps staging latency)
    float cc, ss_, gam;
    coeffs(lamda, theta, h, cc, ss_, gam);
    // rotation powers: R2, R4, R8, R16, R32
    float a2 = cc, b2 = ss_; cmul(cc, ss_, a2, b2);          // R^2
    float a4 = a2, b4 = b2;  cmul(a2, b2, a4, b4);           // R^4
    float a8 = a4, b8 = b4;  cmul(a4, b4, a8, b8);           // R^8
    float a16 = a8, b16 = b8; cmul(a8, b8, a16, b16);        // R^16
    float a32 = a16, b32 = b16; cmul(a16, b16, a32, b32);    // R^32

    CP_WAIT0();
    BARN(1 + q, 128);                   // quarter-local: strip q resident

    // ---- GEMM quarter: 32t x 64c x 64k, 4x4 strided f32x2 micro-tile ----
    const int tsub = r >> 4;            // rows {tsub+8i}
    const int csub = r & 15;            // cols {csub+16i}

    unsigned long long acc[4][4];
#pragma unroll
    for (int i = 0; i < 4; i++)
#pragma unroll
        for (int jb = 0; jb < 4; jb++) acc[i][jb] = 0ull;

#pragma unroll 8
    for (int kq = 16 * q; kq < 16 * q + 16; kq++) {
        int kf = kq * 4;
        ulonglong2 av[4], bv[4];
#pragma unroll
        for (int i = 0; i < 4; i++)
            av[i] = *(const ulonglong2*)&as[(tsub + 8 * i) * STRA + kf];
#pragma unroll
        for (int i = 0; i < 4; i++)
            bv[i] = *(const ulonglong2*)&bs[(csub + 16 * i) * STRA + kf];
#pragma unroll
        for (int i = 0; i < 4; i++)
#pragma unroll
            for (int jb = 0; jb < 4; jb++) {
                FMA2(acc[i][jb], av[i].x, bv[jb].x);
                FMA2(acc[i][jb], av[i].y, bv[jb].y);
            }
    }

    // write quarter partials
#pragma unroll
    for (int i = 0; i < 4; i++)
#pragma unroll
        for (int jb = 0; jb < 4; jb++)
            P[q * P_QS + (tsub + 8 * i) * P_TS + csub + 16 * jb] = f32x2_sum(acc[i][jb]);
    __syncthreads();

    // ---- parallel in-chunk scan: 16 subchunks of 2 steps ----
    float rl1[2], rl2[2];
    {
        float l1 = 0.f, l2 = 0.f;
#pragma unroll
        for (int i = 0; i < 2; i++) {
            int tt = 2 * sc + i;
            float b1v = P[0 * P_QS + tt * P_TS + ch]      + P[1 * P_QS + tt * P_TS + ch]
                      + P[2 * P_QS + tt * P_TS + ch]      + P[3 * P_QS + tt * P_TS + ch];
            float b2v = P[0 * P_QS + tt * P_TS + 32 + ch] + P[1 * P_QS + tt * P_TS + 32 + ch]
                      + P[2 * P_QS + tt * P_TS + 32 + ch] + P[3 * P_QS + tt * P_TS + 32 + ch];
            float n1 = fmaf(cc, l1, fmaf(-ss_, l2, gam * b1v));
            float n2 = fmaf(cc, l2, fmaf( ss_, l1, gam * b2v));
            l1 = n1; l2 = n2;
            rl1[i] = l1; rl2[i] = l2;
        }
        Es[sc * 64 + ch]      = l1;
        Es[sc * 64 + 32 + ch] = l2;
    }
    __syncthreads();

    // subchunk carry: P_start(sc) = sum_{u<sc} R2^(sc-1-u) Es[u]
    {
        float p1 = 0.f, p2 = 0.f;
#pragma unroll
        for (int u = 0; u < 15; u++) {
            if (u < sc) {
                float e1 = Es[u * 64 + ch];
                float e2 = Es[u * 64 + 32 + ch];
                float n1 = fmaf(a2, p1, fmaf(-b2, p2, e1));
                float n2 = fmaf(a2, p2, fmaf( b2, p1, e2));
                p1 = n1; p2 = n2;
            }
        }
#pragma unroll
        for (int i = 0; i < 2; i++) {
            float n1 = fmaf(cc, p1, -ss_ * p2);
            float n2 = fmaf(cc, p2,  ss_ * p1);
            p1 = n1; p2 = n2;
            rl1[i] += p1; rl2[i] += p2;
        }
    }
    // chunk end state (tt = 31) -> g_E
    if (sc == 15) {
        g_E[j * H2 + h]      = rl1[1];
        g_E[j * H2 + HH + h] = rl2[1];
        __threadfence();
    }
    __syncthreads();

    // ---- software grid barrier (128 blocks, all co-resident) ----
    if (tid == 0) {
        __threadfence();
        int ticket = atomicAdd(&g_ctr, 1);
        int target = ((ticket >> 7) + 1) << 7;
        while (*((volatile int*)&g_ctr) < target) { }
        __threadfence();
    }
    __syncthreads();

    // ---- cross-chunk carry ----
    float p1 = 0.f, p2 = 0.f;
#pragma unroll
    for (int i = 0; i < NCHUNK - 1; i++) {
        if (i < j) {
            float e1 = __ldcg(&g_E[i * H2 + h]);
            float e2 = __ldcg(&g_E[i * H2 + HH + h]);
            float n1 = fmaf(a32, p1, fmaf(-b32, p2, e1));
            float n2 = fmaf(a32, p2, fmaf( b32, p1, e2));
            p1 = n1; p2 = n2;
        }
    }
    // rotate carry to subchunk start: p *= R2^sc (binary exponent)
    if (sc & 1) cmul(a2,  b2,  p1, p2);
    if (sc & 2) cmul(a4,  b4,  p1, p2);
    if (sc & 4) cmul(a8,  b8,  p1, p2);
    if (sc & 8) cmul(a16, b16, p1, p2);

    // final single store of out
#pragma unroll
    for (int i = 0; i < 2; i++) {
        float n1 = fmaf(cc, p1, -ss_ * p2);
        float n2 = fmaf(cc, p2,  ss_ * p1);
        p1 = n1; p2 = n2;
        int tt = 2 * sc + i;
        out[(t0 + tt) * H2 + h]      = rl1[i] + p1;
        out[(t0 + tt) * H2 + HH + h] = rl2[i] + p2;
    }
}

// ---------------------------------------------------------------------------
extern "C" void kernel_launch(void* const* d_in, const int* in_sizes, int n_in,
                              void* d_out, int out_size)
{
    const float* x     = (const float*)d_in[0];
    const float* lamda = (const float*)d_in[1];
    const float* theta = (const float*)d_in[2];
    const float* B1    = (const float*)d_in[3];
    const float* B2    = (const float*)d_in[4];
    float* out = (float*)d_out;

    static bool attr_set = false;
    if (!attr_set) {
        cudaFuncSetAttribute(rtrl_kernel,
                             cudaFuncAttributeMaxDynamicSharedMemorySize,
                             SMEM_BYTES);
        attr_set = true;
    }

    dim3 grid(NCHUNK, HH / 32);         // (16, 8) = 128 blocks, all co-resident
    rtrl_kernel<<<grid, NTHR, SMEM_BYTES>>>(x, B1, B2, lamda, theta, out);
}